// round 3
// baseline (speedup 1.0000x reference)
#include <cuda_runtime.h>
#include <cstdint>
#include <cfloat>
#include <math.h>

#define VOC   10000
#define EMB   512
#define HID   1024
#define BATCH 128
#define SEQT  64
#define STEPS 63
#define CTXW  4096
#define G4H   4096
#define NBLK  128
#define NTHR  512
#define NTILE_C 313          // ceil(10000/32)

typedef long long ll;

// ---------------- persistent device scratch (no allocation) ------------------
__device__ __align__(128) float g_hn[BATCH * G4H];
__device__ __align__(128) float g_x[BATCH * EMB];
__device__ __align__(128) float g_h1[2][BATCH * HID];
__device__ __align__(128) float g_h2[2][BATCH * HID];
__device__ __align__(128) float g_pmax[BATCH][NTILE_C];
__device__ __align__(128) int   g_pidx[BATCH][NTILE_C];
__device__ unsigned g_count;
__device__ unsigned g_gen;

__device__ __forceinline__ float sigmf(float x) { return 1.0f / (1.0f + expf(-x)); }

__device__ __forceinline__ void ffma2(ll& d, ll a, ll b) {
    asm("fma.rn.f32x2 %0, %1, %2, %0;" : "+l"(d) : "l"(a), "l"(b));
}
__device__ __forceinline__ ll packf2(float lo, float hi) {
    ll r; asm("mov.b64 %0, {%1, %2};" : "=l"(r) : "f"(lo), "f"(hi)); return r;
}
__device__ __forceinline__ float2 unpackf2(ll v) {
    float2 f; asm("mov.b64 {%0, %1}, %2;" : "=f"(f.x), "=f"(f.y) : "l"(v)); return f;
}

// ---------------- grid-wide sense barrier ------------------------------------
__device__ __forceinline__ void gbar() {
    __syncthreads();
    if (threadIdx.x == 0) {
        __threadfence();
        unsigned gen = *((volatile unsigned*)&g_gen);
        unsigned arrived = atomicAdd(&g_count, 1);
        if (arrived == NBLK - 1) {
            atomicExch(&g_count, 0);
            __threadfence();
            atomicAdd(&g_gen, 1);
        } else {
            while (*((volatile unsigned*)&g_gen) == gen) __nanosleep(64);
        }
        __threadfence();
    }
    __syncthreads();
}

// ---------------- FFMA2 GEMM slice engine ------------------------------------
// C[128 x 32] += A[128 x K] * W^T. MR=4: 2 K-slices of 256 thr; MR=8: 4 slices
// of 128 thr. Accumulators pack row-pairs in f32x2. W duplicated in smem so
// {w,w} pairs come from a single LDS. Register prefetch hides L2 latency.
template<int MR, bool GATED>
__device__ __forceinline__ void gemm_run(
    ll (&acc)[MR/2][4],
    const float* __restrict__ A, int lda,
    const float* __restrict__ W, int ldw, int wcol0,
    int colBase, int growMax,
    int kBeg, int kLen,
    float* __restrict__ sAbuf, float* __restrict__ sWbuf)
{
    constexpr int TPS = (MR == 4) ? 256 : 128;
    constexpr int KC  = (MR == 4) ? 16 : 8;
    const int tid = threadIdx.x;
    const int slice = tid / TPS;
    const int lt = tid % TPS;
    float* sA = sAbuf + slice * (KC * 128);
    float* sW = sWbuf + slice * (KC * 64);
    const int rowg = lt >> 3, colg = lt & 7;
    int a_r, ak;
    if (MR == 4) { a_r = lt >> 1; ak = (lt & 1) * 8; }
    else         { a_r = lt;      ak = 0;            }
    const int w_c = lt & 31, wq = lt >> 5;
    int grow;
    if (GATED) grow = ((w_c >> 3) * HID) + colBase + (w_c & 7);
    else { grow = colBase + w_c; if (grow > growMax) grow = growMax; }
    const float* ap = A + (size_t)a_r * lda + ak + kBeg;
    const float* wp = W + (size_t)grow * ldw + wcol0 + wq * 2 + kBeg;

    float4 pa0 = __ldcg((const float4*)ap);
    float4 pa1 = __ldcg((const float4*)(ap + 4));
    float2 pw  = *(const float2*)wp;

    for (int k0 = 0; k0 < kLen; k0 += KC) {
        __syncthreads();
        {
            float* d = sA + ak * 128 + a_r;
            d[0]       = pa0.x; d[128]     = pa0.y; d[256]     = pa0.z; d[384]     = pa0.w;
            d[512]     = pa1.x; d[640]     = pa1.y; d[768]     = pa1.z; d[896]     = pa1.w;
            sW[(wq*2)*64 + w_c*2]     = pw.x; sW[(wq*2)*64 + w_c*2 + 1]     = pw.x;
            sW[(wq*2+1)*64 + w_c*2]   = pw.y; sW[(wq*2+1)*64 + w_c*2 + 1]   = pw.y;
        }
        __syncthreads();
        if (k0 + KC < kLen) {
            pa0 = __ldcg((const float4*)(ap + k0 + KC));
            pa1 = __ldcg((const float4*)(ap + k0 + KC + 4));
            pw  = *(const float2*)(wp + k0 + KC);
        }
        #pragma unroll
        for (int kk = 0; kk < KC; kk++) {
            longlong2 wA = *(const longlong2*)(sW + kk * 64 + colg * 8);
            longlong2 wB = *(const longlong2*)(sW + kk * 64 + colg * 8 + 4);
            longlong2 a0 = *(const longlong2*)(sA + kk * 128 + rowg * MR);
            ffma2(acc[0][0], a0.x, wA.x); ffma2(acc[0][1], a0.x, wA.y);
            ffma2(acc[0][2], a0.x, wB.x); ffma2(acc[0][3], a0.x, wB.y);
            ffma2(acc[1][0], a0.y, wA.x); ffma2(acc[1][1], a0.y, wA.y);
            ffma2(acc[1][2], a0.y, wB.x); ffma2(acc[1][3], a0.y, wB.y);
            if constexpr (MR == 8) {
                longlong2 a1 = *(const longlong2*)(sA + kk * 128 + rowg * 8 + 4);
                ffma2(acc[2][0], a1.x, wA.x); ffma2(acc[2][1], a1.x, wA.y);
                ffma2(acc[2][2], a1.x, wB.x); ffma2(acc[2][3], a1.x, wB.y);
                ffma2(acc[3][0], a1.y, wA.x); ffma2(acc[3][1], a1.y, wA.y);
                ffma2(acc[3][2], a1.y, wB.x); ffma2(acc[3][3], a1.y, wB.y);
            }
        }
    }
}

__global__ void __launch_bounds__(NTHR, 1) lstm_kernel(
    const float* __restrict__ h_n,   const int* __restrict__ expanded,
    const int* __restrict__ tfmask,  const float* __restrict__ dropm,
    const float* __restrict__ embW,
    const float* __restrict__ Wih1,  const float* __restrict__ Whh1,
    const float* __restrict__ bih1,  const float* __restrict__ bhh1,
    const float* __restrict__ Wih2,  const float* __restrict__ Whh2,
    const float* __restrict__ bih2,  const float* __restrict__ bhh2,
    const float* __restrict__ Wout,  const float* __restrict__ bout,
    float* __restrict__ out)
{
    __shared__ __align__(16) float sAbuf[4096];   // 16 KB: per-slice A tiles
    __shared__ __align__(16) float sWbuf[2048];   //  8 KB: per-slice dup W tiles
    __shared__ __align__(16) ll    sAux[2112];    // 16.9 KB: gate tile / reduce buf
    __shared__ float s_rv[NTHR];
    __shared__ int   s_ri[NTHR];
    __shared__ int   s_tok;
    __shared__ float s_sc;

    const int tid = threadIdx.x;
    const int blk = blockIdx.x;
    const int j0  = blk * 8;
    float* sGf = (float*)sAux;

    // ---------------- init ----------------
    for (int i = blk * NTHR + tid; i < BATCH * HID; i += NBLK * NTHR) {
        g_h1[0][i] = 0.f; g_h2[0][i] = 0.f;
    }
    for (int i = blk * NTHR + tid; i < BATCH * EMB; i += NBLK * NTHR) {
        int b = i / EMB; int e = i - b * EMB;
        int tok = expanded[b * SEQT];
        g_x[i] = dropm[tok] * embW[(size_t)tok * EMB + e];
    }
    {   // g_hn = h_n @ Wih1[:, E:].T (gate-grouped tile per block), + biases
        ll acc[2][4];
        #pragma unroll
        for (int p = 0; p < 2; p++)
            #pragma unroll
            for (int q = 0; q < 4; q++) acc[p][q] = packf2(0.f, 0.f);
        int slice = tid >> 8;
        gemm_run<4, true>(acc, h_n, CTXW, Wih1, EMB + CTXW, EMB,
                          j0, 0, slice * 2048, 2048, sAbuf, sWbuf);
        __syncthreads();
        if (tid < 256) {
            int rowg = tid >> 3, colg = tid & 7;
            #pragma unroll
            for (int p = 0; p < 2; p++)
                #pragma unroll
                for (int q = 0; q < 4; q++) {
                    float2 v = unpackf2(acc[p][q]);
                    sGf[(rowg*4 + 2*p    ) * 33 + colg*4 + q] = v.x;
                    sGf[(rowg*4 + 2*p + 1) * 33 + colg*4 + q] = v.y;
                }
        }
        __syncthreads();
        if (tid >= 256) {
            int lt = tid - 256, rowg = lt >> 3, colg = lt & 7;
            #pragma unroll
            for (int p = 0; p < 2; p++)
                #pragma unroll
                for (int q = 0; q < 4; q++) {
                    float2 v = unpackf2(acc[p][q]);
                    sGf[(rowg*4 + 2*p    ) * 33 + colg*4 + q] += v.x;
                    sGf[(rowg*4 + 2*p + 1) * 33 + colg*4 + q] += v.y;
                }
        }
        __syncthreads();
        #pragma unroll
        for (int jj = 0; jj < 2; jj++) {
            int p = tid + jj * NTHR;
            int r = p >> 3, jl = p & 7;
            #pragma unroll
            for (int g = 0; g < 4; g++) {
                int col = g * HID + j0 + jl;
                g_hn[(size_t)r * G4H + col] =
                    sGf[r * 33 + g * 8 + jl] + bih1[col] + bhh1[col];
            }
        }
    }
    gbar();

    float c1s[2] = {0.f, 0.f};
    float c2s[2] = {0.f, 0.f};

    for (int t = 0; t < STEPS; t++) {
        const float* h1o = g_h1[t & 1];
        float*       h1n = g_h1[(t + 1) & 1];
        const float* h2o = g_h2[t & 1];
        float*       h2n = g_h2[(t + 1) & 1];

        // ---------- phase A: layer-1 gates + cell ----------
        {
            ll acc[2][4];
            if (tid < 256) {
                int rowg = tid >> 3, colg = tid & 7;
                int g = colg >> 1, jlb = (colg & 1) * 4;
                #pragma unroll
                for (int p = 0; p < 2; p++)
                    #pragma unroll
                    for (int q = 0; q < 4; q++) {
                        int col = g * HID + j0 + jlb + q;
                        float lo = g_hn[(size_t)(rowg*4 + 2*p    ) * G4H + col];
                        float hi = g_hn[(size_t)(rowg*4 + 2*p + 1) * G4H + col];
                        acc[p][q] = packf2(lo, hi);
                    }
            } else {
                #pragma unroll
                for (int p = 0; p < 2; p++)
                    #pragma unroll
                    for (int q = 0; q < 4; q++) acc[p][q] = packf2(0.f, 0.f);
            }
            int slice = tid >> 8;
            gemm_run<4, true>(acc, g_x, EMB, Wih1, EMB + CTXW, 0,
                              j0, 0, slice * 256, 256, sAbuf, sWbuf);
            gemm_run<4, true>(acc, h1o, HID, Whh1, HID, 0,
                              j0, 0, slice * 512, 512, sAbuf, sWbuf);
            __syncthreads();
            if (tid < 256) {
                int rowg = tid >> 3, colg = tid & 7;
                #pragma unroll
                for (int p = 0; p < 2; p++)
                    #pragma unroll
                    for (int q = 0; q < 4; q++) {
                        float2 v = unpackf2(acc[p][q]);
                        sGf[(rowg*4 + 2*p    ) * 33 + colg*4 + q] = v.x;
                        sGf[(rowg*4 + 2*p + 1) * 33 + colg*4 + q] = v.y;
                    }
            }
            __syncthreads();
            if (tid >= 256) {
                int lt = tid - 256, rowg = lt >> 3, colg = lt & 7;
                #pragma unroll
                for (int p = 0; p < 2; p++)
                    #pragma unroll
                    for (int q = 0; q < 4; q++) {
                        float2 v = unpackf2(acc[p][q]);
                        sGf[(rowg*4 + 2*p    ) * 33 + colg*4 + q] += v.x;
                        sGf[(rowg*4 + 2*p + 1) * 33 + colg*4 + q] += v.y;
                    }
            }
            __syncthreads();
            #pragma unroll
            for (int jj = 0; jj < 2; jj++) {
                int p = tid + jj * NTHR;
                int r = p >> 3, jl = p & 7;
                float ii = sGf[r*33 +      jl];
                float ff = sGf[r*33 +  8 + jl];
                float gg = sGf[r*33 + 16 + jl];
                float oo = sGf[r*33 + 24 + jl];
                float cn = sigmf(ff) * c1s[jj] + sigmf(ii) * tanhf(gg);
                c1s[jj] = cn;
                h1n[r * HID + j0 + jl] = sigmf(oo) * tanhf(cn);
            }
        }
        gbar();

        // ---------- phase B: layer-2 gates + cell ----------
        {
            ll acc[2][4];
            if (tid < 256) {
                int colg = tid & 7;
                int g = colg >> 1, jlb = (colg & 1) * 4;
                #pragma unroll
                for (int q = 0; q < 4; q++) {
                    int col = g * HID + j0 + jlb + q;
                    float b = bih2[col] + bhh2[col];
                    acc[0][q] = packf2(b, b);
                    acc[1][q] = packf2(b, b);
                }
            } else {
                #pragma unroll
                for (int p = 0; p < 2; p++)
                    #pragma unroll
                    for (int q = 0; q < 4; q++) acc[p][q] = packf2(0.f, 0.f);
            }
            int slice = tid >> 8;
            gemm_run<4, true>(acc, h1n, HID, Wih2, HID, 0,
                              j0, 0, slice * 512, 512, sAbuf, sWbuf);
            gemm_run<4, true>(acc, h2o, HID, Whh2, HID, 0,
                              j0, 0, slice * 512, 512, sAbuf, sWbuf);
            __syncthreads();
            if (tid < 256) {
                int rowg = tid >> 3, colg = tid & 7;
                #pragma unroll
                for (int p = 0; p < 2; p++)
                    #pragma unroll
                    for (int q = 0; q < 4; q++) {
                        float2 v = unpackf2(acc[p][q]);
                        sGf[(rowg*4 + 2*p    ) * 33 + colg*4 + q] = v.x;
                        sGf[(rowg*4 + 2*p + 1) * 33 + colg*4 + q] = v.y;
                    }
            }
            __syncthreads();
            if (tid >= 256) {
                int lt = tid - 256, rowg = lt >> 3, colg = lt & 7;
                #pragma unroll
                for (int p = 0; p < 2; p++)
                    #pragma unroll
                    for (int q = 0; q < 4; q++) {
                        float2 v = unpackf2(acc[p][q]);
                        sGf[(rowg*4 + 2*p    ) * 33 + colg*4 + q] += v.x;
                        sGf[(rowg*4 + 2*p + 1) * 33 + colg*4 + q] += v.y;
                    }
            }
            __syncthreads();
            #pragma unroll
            for (int jj = 0; jj < 2; jj++) {
                int p = tid + jj * NTHR;
                int r = p >> 3, jl = p & 7;
                float ii = sGf[r*33 +      jl];
                float ff = sGf[r*33 +  8 + jl];
                float gg = sGf[r*33 + 16 + jl];
                float oo = sGf[r*33 + 24 + jl];
                float cn = sigmf(ff) * c2s[jj] + sigmf(ii) * tanhf(gg);
                c2s[jj] = cn;
                h2n[r * HID + j0 + jl] = sigmf(oo) * tanhf(cn);
            }
        }
        gbar();

        // ---------- phase C: logits GEMM + per-tile argmax partials ----------
        for (int tile = blk; tile < NTILE_C; tile += NBLK) {
            int n0 = tile * 32;
            int slice = tid >> 7;   // MR=8: 4 slices of 128
            ll acc[4][4];
            if (slice == 0) {
                int colg = tid & 7;
                #pragma unroll
                for (int q = 0; q < 4; q++) {
                    int col = n0 + colg * 4 + q;
                    float b = (col < VOC) ? bout[col] : 0.f;
                    #pragma unroll
                    for (int p = 0; p < 4; p++) acc[p][q] = packf2(b, b);
                }
            } else {
                #pragma unroll
                for (int p = 0; p < 4; p++)
                    #pragma unroll
                    for (int q = 0; q < 4; q++) acc[p][q] = packf2(0.f, 0.f);
            }
            gemm_run<8, false>(acc, h2n, HID, Wout, HID, 0,
                               n0, VOC - 1, slice * 256, 256, sAbuf, sWbuf);
            // staged cross-slice reduction through sAux
            ll* buf = sAux;
            int lt = tid & 127;
            #pragma unroll
            for (int s = 1; s < 4; s++) {
                __syncthreads();
                if (slice == s) {
                    #pragma unroll
                    for (int p = 0; p < 4; p++)
                        #pragma unroll
                        for (int q = 0; q < 4; q++) buf[lt*16 + p*4 + q] = acc[p][q];
                }
                __syncthreads();
                if (slice == 0) {
                    #pragma unroll
                    for (int p = 0; p < 4; p++)
                        #pragma unroll
                        for (int q = 0; q < 4; q++) {
                            float2 m = unpackf2(acc[p][q]);
                            float2 o = unpackf2(buf[lt*16 + p*4 + q]);
                            acc[p][q] = packf2(m.x + o.x, m.y + o.y);
                        }
                }
            }
            if (slice == 0) {
                int rowg = tid >> 3, colg = tid & 7;
                #pragma unroll
                for (int p = 0; p < 4; p++) {
                    float2 v[4];
                    #pragma unroll
                    for (int q = 0; q < 4; q++) v[q] = unpackf2(acc[p][q]);
                    #pragma unroll
                    for (int e = 0; e < 2; e++) {
                        int r = rowg * 8 + 2*p + e;
                        float bv = -FLT_MAX; int bc = 0x7fffffff;
                        size_t ob = ((size_t)t * BATCH + r) * VOC;
                        #pragma unroll
                        for (int q = 0; q < 4; q++) {
                            int col = n0 + colg * 4 + q;
                            float x = e ? v[q].y : v[q].x;
                            if (col < VOC) {
                                out[ob + col] = x;
                                if (x > bv) { bv = x; bc = col; }
                            }
                        }
                        #pragma unroll
                        for (int d = 4; d > 0; d >>= 1) {
                            float ov = __shfl_down_sync(0xffffffffu, bv, d, 8);
                            int   oc = __shfl_down_sync(0xffffffffu, bc, d, 8);
                            if (ov > bv || (ov == bv && oc < bc)) { bv = ov; bc = oc; }
                        }
                        if (colg == 0) { g_pmax[r][tile] = bv; g_pidx[r][tile] = bc; }
                    }
                }
            }
        }
        gbar();

        // ---------- phase D: final argmax + next-input select ----------
        {
            int b = blk;
            float bv = -FLT_MAX; int bc = 0x7fffffff;
            if (tid < NTILE_C) {
                bv = __ldcg(&g_pmax[b][tid]);
                bc = __ldcg(&g_pidx[b][tid]);
            }
            s_rv[tid] = bv; s_ri[tid] = bc;
            __syncthreads();
            for (int s = NTHR / 2; s > 0; s >>= 1) {
                if (tid < s) {
                    float v = s_rv[tid + s]; int c = s_ri[tid + s];
                    if (v > s_rv[tid] || (v == s_rv[tid] && c < s_ri[tid])) {
                        s_rv[tid] = v; s_ri[tid] = c;
                    }
                }
                __syncthreads();
            }
            if (tid == 0) {
                int m = tfmask[t * BATCH + b];
                int tok; float sc;
                if (m == 1) { tok = s_ri[0]; sc = 1.0f; }
                else        { tok = expanded[b * SEQT + t + 1]; sc = dropm[tok]; }
                s_tok = tok; s_sc = sc;
            }
            __syncthreads();
            int tok = s_tok; float sc = s_sc;
            g_x[b * EMB + tid] = sc * embW[(size_t)tok * EMB + tid];
        }
        gbar();
    }
}

extern "C" void kernel_launch(void* const* d_in, const int* in_sizes, int n_in,
                              void* d_out, int out_size) {
    (void)in_sizes; (void)n_in; (void)out_size;
    lstm_kernel<<<NBLK, NTHR>>>(
        (const float*)d_in[0],  (const int*)d_in[1],  (const int*)d_in[2],
        (const float*)d_in[3],  (const float*)d_in[4], (const float*)d_in[5],
        (const float*)d_in[6],  (const float*)d_in[7], (const float*)d_in[8],
        (const float*)d_in[9],  (const float*)d_in[10], (const float*)d_in[11],
        (const float*)d_in[12], (const float*)d_in[13], (const float*)d_in[14],
        (float*)d_out);
}

// round 4
// speedup vs baseline: 1.7709x; 1.7709x over previous
#include <cuda_runtime.h>
#include <cstdint>
#include <cfloat>
#include <math.h>

#define VOC   10000
#define EMB   512
#define HID   1024
#define BATCH 128
#define SEQT  64
#define STEPS 63
#define CTXW  4096
#define G4H   4096
#define NBLK  128
#define NTHR  256
#define NTILE_C 313          // ceil(10000/32)

#define KC        8
#define SA_STRIDE 20         // floats/row: 16 (dup 8k) + 4 pad, even for LDS.64
#define SW_STRIDE 34         // floats/k-row: 32 cols + 2 pad, even for LDS.64
#define SA_SLICE  (128 * SA_STRIDE)   // 2560 floats
#define SW_SLICE  (KC * SW_STRIDE)    // 272 floats

typedef long long ll;

// ---------------- persistent device scratch ----------------------------------
__device__ __align__(128) float g_hn[BATCH * G4H];
__device__ __align__(128) float g_x[BATCH * EMB];
__device__ __align__(128) float g_h1[2][BATCH * HID];
__device__ __align__(128) float g_h2[2][BATCH * HID];
__device__ __align__(128) float g_pmax[BATCH][NTILE_C];
__device__ __align__(128) int   g_pidx[BATCH][NTILE_C];
__device__ unsigned g_count;
__device__ unsigned g_gen;

__device__ __forceinline__ float sigmf(float x) { return 1.0f / (1.0f + expf(-x)); }

__device__ __forceinline__ void ffma2(ll& d, ll a, ll b) {
    asm("fma.rn.f32x2 %0, %1, %2, %0;" : "+l"(d) : "l"(a), "l"(b));
}
__device__ __forceinline__ ll packf2(float lo, float hi) {
    ll r; asm("mov.b64 %0, {%1, %2};" : "=l"(r) : "f"(lo), "f"(hi)); return r;
}
__device__ __forceinline__ float2 unpackf2(ll v) {
    float2 f; asm("mov.b64 {%0, %1}, %2;" : "=f"(f.x), "=f"(f.y) : "l"(v)); return f;
}

// ---------------- grid-wide sense barrier ------------------------------------
__device__ __forceinline__ void gbar() {
    __syncthreads();
    if (threadIdx.x == 0) {
        __threadfence();
        unsigned gen = *((volatile unsigned*)&g_gen);
        unsigned arrived = atomicAdd(&g_count, 1);
        if (arrived == NBLK - 1) {
            atomicExch(&g_count, 0);
            __threadfence();
            atomicAdd(&g_gen, 1);
        } else {
            while (*((volatile unsigned*)&g_gen) == gen) __nanosleep(64);
        }
        __threadfence();
    }
    __syncthreads();
}

// ---------------- FFMA2 GEMM engine ------------------------------------------
// C[128 x 32] += A[128 x K] * W^T with 4 K-slices of 64 threads.
// Thread (rg,cg): rows {rg + 16*i, i<8}, col-pairs {cg*8 + 2j, j<4}.
// A smem: duplicated pairs [row][2k] (stride 20) -> av LDS.64 gives {a,a}.
// W smem: k-major [k][col] (stride 34)          -> wv LDS.64 gives {w0,w1}.
// GATED: tile col c maps to W row (c>>3)*HID + colBase + (c&7).
template<bool GATED>
__device__ __forceinline__ void gemm_run(ll (&acc)[8][4],
    const float* __restrict__ A, int lda,
    const float* __restrict__ W, int ldw, int wcol0,
    int colBase, int growMax, int kBeg, int kLen,
    float* __restrict__ sAbuf, float* __restrict__ sWbuf)
{
    const int tid   = threadIdx.x;
    const int slice = tid >> 6;
    const int lt    = tid & 63;
    const int rg    = lt >> 2;
    const int cg    = lt & 3;
    float* sA = sAbuf + slice * SA_SLICE;
    float* sW = sWbuf + slice * SW_SLICE;

    const int arow = lt >> 1, akq = lt & 1;   // A loader: rows arow+{0,32,64,96}
    const int wrow = lt >> 1, wkq = lt & 1;   // W loader: 32 rows, 2 k-quads
    int grow;
    if (GATED) grow = ((wrow >> 3) * HID) + colBase + (wrow & 7);
    else { grow = colBase + wrow; if (grow > growMax) grow = growMax; }
    const float* ap = A + (size_t)arow * lda + kBeg + akq * 4;
    const float* wp = W + (size_t)grow * ldw + wcol0 + kBeg + wkq * 4;

    float4 pa0 = __ldcg((const float4*)(ap));
    float4 pa1 = __ldcg((const float4*)(ap + (size_t)32 * lda));
    float4 pa2 = __ldcg((const float4*)(ap + (size_t)64 * lda));
    float4 pa3 = __ldcg((const float4*)(ap + (size_t)96 * lda));
    float4 pw  = *(const float4*)(wp);

    for (int k0 = 0; k0 < kLen; k0 += KC) {
        __syncthreads();
        {   // store A duplicated pairs
            ll* d0 = (ll*)(sA + arow * SA_STRIDE + akq * 8);
            d0[0] = packf2(pa0.x, pa0.x); d0[1] = packf2(pa0.y, pa0.y);
            d0[2] = packf2(pa0.z, pa0.z); d0[3] = packf2(pa0.w, pa0.w);
            ll* d1 = (ll*)(sA + (arow + 32) * SA_STRIDE + akq * 8);
            d1[0] = packf2(pa1.x, pa1.x); d1[1] = packf2(pa1.y, pa1.y);
            d1[2] = packf2(pa1.z, pa1.z); d1[3] = packf2(pa1.w, pa1.w);
            ll* d2 = (ll*)(sA + (arow + 64) * SA_STRIDE + akq * 8);
            d2[0] = packf2(pa2.x, pa2.x); d2[1] = packf2(pa2.y, pa2.y);
            d2[2] = packf2(pa2.z, pa2.z); d2[3] = packf2(pa2.w, pa2.w);
            ll* d3 = (ll*)(sA + (arow + 96) * SA_STRIDE + akq * 8);
            d3[0] = packf2(pa3.x, pa3.x); d3[1] = packf2(pa3.y, pa3.y);
            d3[2] = packf2(pa3.z, pa3.z); d3[3] = packf2(pa3.w, pa3.w);
            // store W transposed to [k][col]
            sW[(wkq * 4 + 0) * SW_STRIDE + wrow] = pw.x;
            sW[(wkq * 4 + 1) * SW_STRIDE + wrow] = pw.y;
            sW[(wkq * 4 + 2) * SW_STRIDE + wrow] = pw.z;
            sW[(wkq * 4 + 3) * SW_STRIDE + wrow] = pw.w;
        }
        __syncthreads();
        if (k0 + KC < kLen) {
            pa0 = __ldcg((const float4*)(ap + k0 + KC));
            pa1 = __ldcg((const float4*)(ap + (size_t)32 * lda + k0 + KC));
            pa2 = __ldcg((const float4*)(ap + (size_t)64 * lda + k0 + KC));
            pa3 = __ldcg((const float4*)(ap + (size_t)96 * lda + k0 + KC));
            pw  = *(const float4*)(wp + k0 + KC);
        }
        #pragma unroll
        for (int kk = 0; kk < KC; kk++) {
            ll wv[4], av[8];
            #pragma unroll
            for (int j = 0; j < 4; j++)
                wv[j] = *(const ll*)(sW + kk * SW_STRIDE + cg * 8 + 2 * j);
            #pragma unroll
            for (int i = 0; i < 8; i++)
                av[i] = *(const ll*)(sA + (rg + 16 * i) * SA_STRIDE + 2 * kk);
            #pragma unroll
            for (int i = 0; i < 8; i++)
                #pragma unroll
                for (int j = 0; j < 4; j++)
                    ffma2(acc[i][j], av[i], wv[j]);
        }
    }
}

// Staged cross-slice reduction: slices 1..3 dump into red (aliased over sA),
// slice 0 accumulates. Caller must have a gemm-final state (sA dead).
__device__ __forceinline__ void reduce_slices(ll (&acc)[8][4], ll* red) {
    const int tid = threadIdx.x;
    const int slice = tid >> 6;
    const int lt = tid & 63;
    #pragma unroll
    for (int s = 1; s < 4; s++) {
        __syncthreads();
        if (slice == s) {
            #pragma unroll
            for (int i = 0; i < 8; i++)
                #pragma unroll
                for (int j = 0; j < 4; j++)
                    red[lt * 32 + i * 4 + j] = acc[i][j];
        }
        __syncthreads();
        if (slice == 0) {
            #pragma unroll
            for (int i = 0; i < 8; i++)
                #pragma unroll
                for (int j = 0; j < 4; j++) {
                    float2 a = unpackf2(acc[i][j]);
                    float2 b = unpackf2(red[lt * 32 + i * 4 + j]);
                    acc[i][j] = packf2(a.x + b.x, a.y + b.y);
                }
        }
    }
}

__global__ void __launch_bounds__(NTHR, 1) lstm_kernel(
    const float* __restrict__ h_n,   const int* __restrict__ expanded,
    const int* __restrict__ tfmask,  const float* __restrict__ dropm,
    const float* __restrict__ embW,
    const float* __restrict__ Wih1,  const float* __restrict__ Whh1,
    const float* __restrict__ bih1,  const float* __restrict__ bhh1,
    const float* __restrict__ Wih2,  const float* __restrict__ Whh2,
    const float* __restrict__ bih2,  const float* __restrict__ bhh2,
    const float* __restrict__ Wout,  const float* __restrict__ bout,
    float* __restrict__ out)
{
    __shared__ __align__(16) float sAbuf[4 * SA_SLICE];  // 40960 B
    __shared__ __align__(16) float sWbuf[4 * SW_SLICE];  //  4352 B
    __shared__ float s_rv[NTHR];
    __shared__ int   s_ri[NTHR];
    __shared__ int   s_tok;
    __shared__ float s_sc;

    ll*    red = (ll*)sAbuf;            // 16 KB reduction stage (aliased)
    float* sGf = sAbuf + 4096;          // 128x33 gate tile (aliased, disjoint)

    const int tid = threadIdx.x;
    const int blk = blockIdx.x;
    const int j0  = blk * 8;
    const int slice = tid >> 6;
    const int lt = tid & 63;
    const int rg = lt >> 2;
    const int cg = lt & 3;

    // ---------------- init ----------------
    for (int i = blk * NTHR + tid; i < BATCH * HID; i += NBLK * NTHR) {
        g_h1[0][i] = 0.f; g_h2[0][i] = 0.f;
    }
    for (int i = blk * NTHR + tid; i < BATCH * EMB; i += NBLK * NTHR) {
        int b = i / EMB; int e = i - b * EMB;
        int tok = expanded[b * SEQT];
        g_x[i] = dropm[tok] * embW[(size_t)tok * EMB + e];
    }
    {   // g_hn = h_n @ Wih1[:, E:].T + bih1 + bhh1 (gate tile for this block)
        ll acc[8][4];
        #pragma unroll
        for (int i = 0; i < 8; i++)
            #pragma unroll
            for (int j = 0; j < 4; j++) acc[i][j] = packf2(0.f, 0.f);
        gemm_run<true>(acc, h_n, CTXW, Wih1, EMB + CTXW, EMB,
                       j0, 0, slice * 1024, 1024, sAbuf, sWbuf);
        reduce_slices(acc, red);
        __syncthreads();
        if (slice == 0) {
            #pragma unroll
            for (int i = 0; i < 8; i++) {
                int r = rg + 16 * i;
                #pragma unroll
                for (int j = 0; j < 4; j++) {
                    int c = cg * 8 + 2 * j;
                    int base = (c >> 3) * HID + j0 + (c & 7);
                    float2 v = unpackf2(acc[i][j]);
                    g_hn[(size_t)r * G4H + base]     = v.x + bih1[base]     + bhh1[base];
                    g_hn[(size_t)r * G4H + base + 1] = v.y + bih1[base + 1] + bhh1[base + 1];
                }
            }
        }
    }
    gbar();

    float c1s[4] = {0.f, 0.f, 0.f, 0.f};
    float c2s[4] = {0.f, 0.f, 0.f, 0.f};

    for (int t = 0; t < STEPS; t++) {
        const float* h1o = g_h1[t & 1];
        float*       h1n = g_h1[(t + 1) & 1];
        const float* h2o = g_h2[t & 1];
        float*       h2n = g_h2[(t + 1) & 1];

        // ---------- phase A: layer-1 gates + cell ----------
        {
            ll acc[8][4];
            if (slice == 0) {
                #pragma unroll
                for (int i = 0; i < 8; i++) {
                    int r = rg + 16 * i;
                    #pragma unroll
                    for (int j = 0; j < 4; j++) {
                        int c = cg * 8 + 2 * j;
                        int base = (c >> 3) * HID + j0 + (c & 7);
                        acc[i][j] = packf2(g_hn[(size_t)r * G4H + base],
                                           g_hn[(size_t)r * G4H + base + 1]);
                    }
                }
            } else {
                #pragma unroll
                for (int i = 0; i < 8; i++)
                    #pragma unroll
                    for (int j = 0; j < 4; j++) acc[i][j] = packf2(0.f, 0.f);
            }
            gemm_run<true>(acc, g_x, EMB, Wih1, EMB + CTXW, 0,
                           j0, 0, slice * 128, 128, sAbuf, sWbuf);
            gemm_run<true>(acc, h1o, HID, Whh1, HID, 0,
                           j0, 0, slice * 256, 256, sAbuf, sWbuf);
            reduce_slices(acc, red);
            __syncthreads();
            if (slice == 0) {
                #pragma unroll
                for (int i = 0; i < 8; i++) {
                    int r = rg + 16 * i;
                    #pragma unroll
                    for (int j = 0; j < 4; j++) {
                        int c = cg * 8 + 2 * j;
                        float2 v = unpackf2(acc[i][j]);
                        sGf[r * 33 + c]     = v.x;
                        sGf[r * 33 + c + 1] = v.y;
                    }
                }
            }
            __syncthreads();
            #pragma unroll
            for (int jj = 0; jj < 4; jj++) {
                int p = tid + jj * NTHR;
                int r = p >> 3, jl = p & 7;
                float ii = sGf[r * 33 +      jl];
                float ff = sGf[r * 33 +  8 + jl];
                float gg = sGf[r * 33 + 16 + jl];
                float oo = sGf[r * 33 + 24 + jl];
                float cn = sigmf(ff) * c1s[jj] + sigmf(ii) * tanhf(gg);
                c1s[jj] = cn;
                h1n[r * HID + j0 + jl] = sigmf(oo) * tanhf(cn);
            }
        }
        gbar();

        // ---------- phase B: layer-2 gates + cell ----------
        {
            ll acc[8][4];
            if (slice == 0) {
                #pragma unroll
                for (int i = 0; i < 8; i++)
                    #pragma unroll
                    for (int j = 0; j < 4; j++) {
                        int c = cg * 8 + 2 * j;
                        int base = (c >> 3) * HID + j0 + (c & 7);
                        acc[i][j] = packf2(bih2[base] + bhh2[base],
                                           bih2[base + 1] + bhh2[base + 1]);
                    }
            } else {
                #pragma unroll
                for (int i = 0; i < 8; i++)
                    #pragma unroll
                    for (int j = 0; j < 4; j++) acc[i][j] = packf2(0.f, 0.f);
            }
            gemm_run<true>(acc, h1n, HID, Wih2, HID, 0,
                           j0, 0, slice * 256, 256, sAbuf, sWbuf);
            gemm_run<true>(acc, h2o, HID, Whh2, HID, 0,
                           j0, 0, slice * 256, 256, sAbuf, sWbuf);
            reduce_slices(acc, red);
            __syncthreads();
            if (slice == 0) {
                #pragma unroll
                for (int i = 0; i < 8; i++) {
                    int r = rg + 16 * i;
                    #pragma unroll
                    for (int j = 0; j < 4; j++) {
                        int c = cg * 8 + 2 * j;
                        float2 v = unpackf2(acc[i][j]);
                        sGf[r * 33 + c]     = v.x;
                        sGf[r * 33 + c + 1] = v.y;
                    }
                }
            }
            __syncthreads();
            #pragma unroll
            for (int jj = 0; jj < 4; jj++) {
                int p = tid + jj * NTHR;
                int r = p >> 3, jl = p & 7;
                float ii = sGf[r * 33 +      jl];
                float ff = sGf[r * 33 +  8 + jl];
                float gg = sGf[r * 33 + 16 + jl];
                float oo = sGf[r * 33 + 24 + jl];
                float cn = sigmf(ff) * c2s[jj] + sigmf(ii) * tanhf(gg);
                c2s[jj] = cn;
                h2n[r * HID + j0 + jl] = sigmf(oo) * tanhf(cn);
            }
        }
        gbar();

        // ---------- phase C: logits GEMM + per-tile argmax partials ----------
        for (int tile = blk; tile < NTILE_C; tile += NBLK) {
            int n0 = tile * 32;
            ll acc[8][4];
            if (slice == 0) {
                #pragma unroll
                for (int j = 0; j < 4; j++) {
                    int c = cg * 8 + 2 * j;
                    float b0 = (n0 + c     < VOC) ? bout[n0 + c]     : 0.f;
                    float b1 = (n0 + c + 1 < VOC) ? bout[n0 + c + 1] : 0.f;
                    #pragma unroll
                    for (int i = 0; i < 8; i++) acc[i][j] = packf2(b0, b1);
                }
            } else {
                #pragma unroll
                for (int i = 0; i < 8; i++)
                    #pragma unroll
                    for (int j = 0; j < 4; j++) acc[i][j] = packf2(0.f, 0.f);
            }
            gemm_run<false>(acc, h2n, HID, Wout, HID, 0,
                            n0, VOC - 1, slice * 256, 256, sAbuf, sWbuf);
            reduce_slices(acc, red);
            if (slice == 0) {
                bool full = (n0 + 32 <= VOC);
                #pragma unroll
                for (int i = 0; i < 8; i++) {
                    int r = rg + 16 * i;
                    size_t ob = ((size_t)t * BATCH + r) * VOC + n0 + cg * 8;
                    float2 v0 = unpackf2(acc[i][0]);
                    float2 v1 = unpackf2(acc[i][1]);
                    float2 v2 = unpackf2(acc[i][2]);
                    float2 v3 = unpackf2(acc[i][3]);
                    float vv[8] = {v0.x, v0.y, v1.x, v1.y, v2.x, v2.y, v3.x, v3.y};
                    float bv = -FLT_MAX; int bc = 0x7fffffff;
                    if (full) {
                        float4 o0 = make_float4(vv[0], vv[1], vv[2], vv[3]);
                        float4 o1 = make_float4(vv[4], vv[5], vv[6], vv[7]);
                        *(float4*)(out + ob)     = o0;
                        *(float4*)(out + ob + 4) = o1;
                        #pragma unroll
                        for (int q = 0; q < 8; q++) {
                            if (vv[q] > bv) { bv = vv[q]; bc = n0 + cg * 8 + q; }
                        }
                    } else {
                        #pragma unroll
                        for (int q = 0; q < 8; q++) {
                            int col = n0 + cg * 8 + q;
                            if (col < VOC) {
                                out[((size_t)t * BATCH + r) * VOC + col] = vv[q];
                                if (vv[q] > bv) { bv = vv[q]; bc = col; }
                            }
                        }
                    }
                    #pragma unroll
                    for (int d = 2; d > 0; d >>= 1) {
                        float ov = __shfl_down_sync(0xffffffffu, bv, d, 4);
                        int   oc = __shfl_down_sync(0xffffffffu, bc, d, 4);
                        if (ov > bv || (ov == bv && oc < bc)) { bv = ov; bc = oc; }
                    }
                    if (cg == 0) { g_pmax[r][tile] = bv; g_pidx[r][tile] = bc; }
                }
            }
        }
        gbar();

        // ---------- phase D: final argmax + next-input select ----------
        {
            int b = blk;
            float bv = -FLT_MAX; int bc = 0x7fffffff;
            for (int tile = tid; tile < NTILE_C; tile += NTHR) {
                float v = __ldcg(&g_pmax[b][tile]);
                int   c = __ldcg(&g_pidx[b][tile]);
                if (v > bv || (v == bv && c < bc)) { bv = v; bc = c; }
            }
            s_rv[tid] = bv; s_ri[tid] = bc;
            __syncthreads();
            for (int s = NTHR / 2; s > 0; s >>= 1) {
                if (tid < s) {
                    float v = s_rv[tid + s]; int c = s_ri[tid + s];
                    if (v > s_rv[tid] || (v == s_rv[tid] && c < s_ri[tid])) {
                        s_rv[tid] = v; s_ri[tid] = c;
                    }
                }
                __syncthreads();
            }
            if (tid == 0) {
                int m = tfmask[t * BATCH + b];
                int tok; float sc;
                if (m == 1) { tok = s_ri[0]; sc = 1.0f; }
                else        { tok = expanded[b * SEQT + t + 1]; sc = dropm[tok]; }
                s_tok = tok; s_sc = sc;
            }
            __syncthreads();
            int tok = s_tok; float sc = s_sc;
            for (int e = tid; e < EMB; e += NTHR)
                g_x[b * EMB + e] = sc * embW[(size_t)tok * EMB + e];
        }
        gbar();
    }
}

extern "C" void kernel_launch(void* const* d_in, const int* in_sizes, int n_in,
                              void* d_out, int out_size) {
    (void)in_sizes; (void)n_in; (void)out_size;
    lstm_kernel<<<NBLK, NTHR>>>(
        (const float*)d_in[0],  (const int*)d_in[1],  (const int*)d_in[2],
        (const float*)d_in[3],  (const float*)d_in[4], (const float*)d_in[5],
        (const float*)d_in[6],  (const float*)d_in[7], (const float*)d_in[8],
        (const float*)d_in[9],  (const float*)d_in[10], (const float*)d_in[11],
        (const float*)d_in[12], (const float*)d_in[13], (const float*)d_in[14],
        (float*)d_out);
}

// round 5
// speedup vs baseline: 1.9207x; 1.0846x over previous
#include <cuda_runtime.h>
#include <cstdint>
#include <cfloat>
#include <math.h>

#define VOC   10000
#define EMB   512
#define HID   1024
#define BATCH 128
#define SEQT  64
#define STEPS 63
#define CTXW  4096
#define G4H   4096
#define NBLK  128
#define NTHR  256
#define NTILE_C 313          // ceil(10000/32)

#define KC        16
#define SA_STRIDE 130        // floats per k-row: 128 rows + 2 pad (S%4==2: no STS conflicts)
#define SW_STRIDE 34         // floats per k-row: 32 cols + 2 pad (even for LDS.64)
#define SA_SLICE  (KC * SA_STRIDE)   // 2080 floats
#define SW_SLICE  (KC * SW_STRIDE)   // 544 floats

typedef long long ll;

// ---------------- persistent device scratch ----------------------------------
__device__ __align__(128) float g_hn[BATCH * G4H];
__device__ __align__(128) float g_x[BATCH * EMB];
__device__ __align__(128) float g_h1[2][BATCH * HID];
__device__ __align__(128) float g_h2[2][BATCH * HID];
__device__ __align__(128) float g_pmax[BATCH][NTILE_C];
__device__ __align__(128) int   g_pidx[BATCH][NTILE_C];
__device__ int g_ctrC[STEPS];
__device__ unsigned g_count;
__device__ unsigned g_gen;

__device__ __forceinline__ float sigmf(float x) { return 1.0f / (1.0f + expf(-x)); }

__device__ __forceinline__ void ffma2(ll& d, ll a, ll b) {
    asm("fma.rn.f32x2 %0, %1, %2, %0;" : "+l"(d) : "l"(a), "l"(b));
}
__device__ __forceinline__ ll packf2(float lo, float hi) {
    ll r; asm("mov.b64 %0, {%1, %2};" : "=l"(r) : "f"(lo), "f"(hi)); return r;
}
__device__ __forceinline__ float2 unpackf2(ll v) {
    float2 f; asm("mov.b64 {%0, %1}, %2;" : "=f"(f.x), "=f"(f.y) : "l"(v)); return f;
}

// ---------------- grid-wide sense barrier ------------------------------------
__device__ __forceinline__ void gbar() {
    __syncthreads();
    if (threadIdx.x == 0) {
        __threadfence();
        unsigned gen = *((volatile unsigned*)&g_gen);
        unsigned arrived = atomicAdd(&g_count, 1);
        if (arrived == NBLK - 1) {
            atomicExch(&g_count, 0);
            __threadfence();
            atomicAdd(&g_gen, 1);
        } else {
            while (*((volatile unsigned*)&g_gen) == gen) __nanosleep(64);
        }
        __threadfence();
    }
    __syncthreads();
}

// ---------------- FFMA2 GEMM engine ------------------------------------------
// C[128 x 32] += A[128 x K] * W^T with 4 K-slices of 64 threads.
// Thread (rg,cg): rows {rg + 16*i, i<8}, col-pairs {cg*8 + 2j, j<4}.
// A smem: k-major [k][row] (stride 130)  -> av = LDS.32 + pack {a,a}.
// W smem: k-major [k][col] (stride 34)   -> wv = LDS.64 natural {w0,w1}.
// GATED: tile col c maps to W row (c>>3)*HID + colBase + (c&7).
template<bool GATED>
__device__ __forceinline__ void gemm_run(ll (&acc)[8][4],
    const float* __restrict__ A, int lda,
    const float* __restrict__ W, int ldw, int wcol0,
    int colBase, int growMax, int kBeg, int kLen,
    float* __restrict__ sAbuf, float* __restrict__ sWbuf)
{
    const int tid   = threadIdx.x;
    const int slice = tid >> 6;
    const int lt    = tid & 63;
    const int rg    = lt >> 2;        // 0..15
    const int cg    = lt & 3;
    float* sA = sAbuf + slice * SA_SLICE;
    float* sW = sWbuf + slice * SW_SLICE;

    const int arow = lt >> 1;         // 0..31 (+32/64/96)
    const int akq  = (lt & 1) * 8;    // k-offset 0 or 8
    const int wrow = lt >> 1;         // 0..31 cols
    const int wkq  = (lt & 1) * 8;
    int grow;
    if (GATED) grow = ((wrow >> 3) * HID) + colBase + (wrow & 7);
    else { grow = colBase + wrow; if (grow > growMax) grow = growMax; }
    const float* ap = A + (size_t)arow * lda + kBeg + akq;
    const float* wp = W + (size_t)grow * ldw + wcol0 + kBeg + wkq;

    float4 pa[4][2];
    float4 pw[2];
    #pragma unroll
    for (int r = 0; r < 4; r++) {
        pa[r][0] = __ldcg((const float4*)(ap + (size_t)r * 32 * lda));
        pa[r][1] = __ldcg((const float4*)(ap + (size_t)r * 32 * lda + 4));
    }
    pw[0] = *(const float4*)(wp);
    pw[1] = *(const float4*)(wp + 4);

    for (int k0 = 0; k0 < kLen; k0 += KC) {
        __syncthreads();
        #pragma unroll
        for (int r = 0; r < 4; r++) {
            float* d = sA + arow + r * 32;
            d[(akq + 0) * SA_STRIDE] = pa[r][0].x;
            d[(akq + 1) * SA_STRIDE] = pa[r][0].y;
            d[(akq + 2) * SA_STRIDE] = pa[r][0].z;
            d[(akq + 3) * SA_STRIDE] = pa[r][0].w;
            d[(akq + 4) * SA_STRIDE] = pa[r][1].x;
            d[(akq + 5) * SA_STRIDE] = pa[r][1].y;
            d[(akq + 6) * SA_STRIDE] = pa[r][1].z;
            d[(akq + 7) * SA_STRIDE] = pa[r][1].w;
        }
        {
            float* d = sW + wrow;
            d[(wkq + 0) * SW_STRIDE] = pw[0].x;
            d[(wkq + 1) * SW_STRIDE] = pw[0].y;
            d[(wkq + 2) * SW_STRIDE] = pw[0].z;
            d[(wkq + 3) * SW_STRIDE] = pw[0].w;
            d[(wkq + 4) * SW_STRIDE] = pw[1].x;
            d[(wkq + 5) * SW_STRIDE] = pw[1].y;
            d[(wkq + 6) * SW_STRIDE] = pw[1].z;
            d[(wkq + 7) * SW_STRIDE] = pw[1].w;
        }
        __syncthreads();
        if (k0 + KC < kLen) {
            #pragma unroll
            for (int r = 0; r < 4; r++) {
                pa[r][0] = __ldcg((const float4*)(ap + (size_t)r * 32 * lda + k0 + KC));
                pa[r][1] = __ldcg((const float4*)(ap + (size_t)r * 32 * lda + k0 + KC + 4));
            }
            pw[0] = *(const float4*)(wp + k0 + KC);
            pw[1] = *(const float4*)(wp + k0 + KC + 4);
        }
        #pragma unroll 4
        for (int kk = 0; kk < KC; kk++) {
            ll wv[4];
            #pragma unroll
            for (int j = 0; j < 4; j++)
                wv[j] = *(const ll*)(sW + kk * SW_STRIDE + cg * 8 + 2 * j);
            #pragma unroll
            for (int i = 0; i < 8; i++) {
                float a = sA[kk * SA_STRIDE + rg + 16 * i];
                ll av = packf2(a, a);
                ffma2(acc[i][0], av, wv[0]);
                ffma2(acc[i][1], av, wv[1]);
                ffma2(acc[i][2], av, wv[2]);
                ffma2(acc[i][3], av, wv[3]);
            }
        }
    }
}

// Staged cross-slice reduction through red (aliased over dead sA).
__device__ __forceinline__ void reduce_slices(ll (&acc)[8][4], ll* red) {
    const int tid = threadIdx.x;
    const int slice = tid >> 6;
    const int lt = tid & 63;
    #pragma unroll
    for (int s = 1; s < 4; s++) {
        __syncthreads();
        if (slice == s) {
            #pragma unroll
            for (int i = 0; i < 8; i++)
                #pragma unroll
                for (int j = 0; j < 4; j++)
                    red[lt * 32 + i * 4 + j] = acc[i][j];
        }
        __syncthreads();
        if (slice == 0) {
            #pragma unroll
            for (int i = 0; i < 8; i++)
                #pragma unroll
                for (int j = 0; j < 4; j++) {
                    float2 a = unpackf2(acc[i][j]);
                    float2 b = unpackf2(red[lt * 32 + i * 4 + j]);
                    acc[i][j] = packf2(a.x + b.x, a.y + b.y);
                }
        }
    }
}

__global__ void __launch_bounds__(NTHR, 1) lstm_kernel(
    const float* __restrict__ h_n,   const int* __restrict__ expanded,
    const int* __restrict__ tfmask,  const float* __restrict__ dropm,
    const float* __restrict__ embW,
    const float* __restrict__ Wih1,  const float* __restrict__ Whh1,
    const float* __restrict__ bih1,  const float* __restrict__ bhh1,
    const float* __restrict__ Wih2,  const float* __restrict__ Whh2,
    const float* __restrict__ bih2,  const float* __restrict__ bhh2,
    const float* __restrict__ Wout,  const float* __restrict__ bout,
    float* __restrict__ out)
{
    __shared__ __align__(16) float sAbuf[4 * SA_SLICE];  // 33280 B
    __shared__ __align__(16) float sWbuf[4 * SW_SLICE];  //  8704 B
    __shared__ float s_rv[NTHR];
    __shared__ int   s_ri[NTHR];
    __shared__ int   s_tok, s_tile;
    __shared__ float s_sc;

    ll*    red = (ll*)sAbuf;            // 16 KB reduction stage (aliased)
    float* sGf = sAbuf + 4096;          // 128x33 gate tile (floats 4096..8320)

    const int tid = threadIdx.x;
    const int blk = blockIdx.x;
    const int j0  = blk * 8;
    const int slice = tid >> 6;
    const int lt = tid & 63;
    const int rg = lt >> 2;
    const int cg = lt & 3;

    // ---------------- init ----------------
    for (int i = blk * NTHR + tid; i < BATCH * HID; i += NBLK * NTHR) {
        g_h1[0][i] = 0.f; g_h2[0][i] = 0.f;
    }
    for (int i = blk * NTHR + tid; i < BATCH * EMB; i += NBLK * NTHR) {
        int b = i / EMB; int e = i - b * EMB;
        int tok = expanded[b * SEQT];
        g_x[i] = dropm[tok] * embW[(size_t)tok * EMB + e];
    }
    if (blk == 0) {
        for (int i = tid; i < STEPS; i += NTHR) g_ctrC[i] = 0;
    }
    {   // g_hn = h_n @ Wih1[:, E:].T + bih1 + bhh1 (gate tile for this block)
        ll acc[8][4];
        #pragma unroll
        for (int i = 0; i < 8; i++)
            #pragma unroll
            for (int j = 0; j < 4; j++) acc[i][j] = packf2(0.f, 0.f);
        gemm_run<true>(acc, h_n, CTXW, Wih1, EMB + CTXW, EMB,
                       j0, 0, slice * 1024, 1024, sAbuf, sWbuf);
        reduce_slices(acc, red);
        __syncthreads();
        if (slice == 0) {
            #pragma unroll
            for (int i = 0; i < 8; i++) {
                int r = rg + 16 * i;
                #pragma unroll
                for (int j = 0; j < 4; j++) {
                    int c = cg * 8 + 2 * j;
                    int base = (c >> 3) * HID + j0 + (c & 7);
                    float2 v = unpackf2(acc[i][j]);
                    g_hn[(size_t)r * G4H + base]     = v.x + bih1[base]     + bhh1[base];
                    g_hn[(size_t)r * G4H + base + 1] = v.y + bih1[base + 1] + bhh1[base + 1];
                }
            }
        }
    }
    gbar();

    float c1s[4] = {0.f, 0.f, 0.f, 0.f};
    float c2s[4] = {0.f, 0.f, 0.f, 0.f};

    for (int t = 0; t < STEPS; t++) {
        const float* h1o = g_h1[t & 1];
        float*       h1n = g_h1[(t + 1) & 1];
        const float* h2o = g_h2[t & 1];
        float*       h2n = g_h2[(t + 1) & 1];

        // ---------- phase A: layer-1 gates + cell ----------
        {
            ll acc[8][4];
            #pragma unroll
            for (int i = 0; i < 8; i++) {
                if ((i >> 1) == slice) {        // distribute g_hn preload
                    int r = rg + 16 * i;
                    #pragma unroll
                    for (int j = 0; j < 4; j++) {
                        int c = cg * 8 + 2 * j;
                        int base = (c >> 3) * HID + j0 + (c & 7);
                        acc[i][j] = packf2(__ldcg(&g_hn[(size_t)r * G4H + base]),
                                           __ldcg(&g_hn[(size_t)r * G4H + base + 1]));
                    }
                } else {
                    #pragma unroll
                    for (int j = 0; j < 4; j++) acc[i][j] = packf2(0.f, 0.f);
                }
            }
            gemm_run<true>(acc, g_x, EMB, Wih1, EMB + CTXW, 0,
                           j0, 0, slice * 128, 128, sAbuf, sWbuf);
            gemm_run<true>(acc, h1o, HID, Whh1, HID, 0,
                           j0, 0, slice * 256, 256, sAbuf, sWbuf);
            reduce_slices(acc, red);
            __syncthreads();
            if (slice == 0) {
                #pragma unroll
                for (int i = 0; i < 8; i++) {
                    int r = rg + 16 * i;
                    #pragma unroll
                    for (int j = 0; j < 4; j++) {
                        int c = cg * 8 + 2 * j;
                        float2 v = unpackf2(acc[i][j]);
                        sGf[r * 33 + c]     = v.x;
                        sGf[r * 33 + c + 1] = v.y;
                    }
                }
            }
            __syncthreads();
            #pragma unroll
            for (int jj = 0; jj < 4; jj++) {
                int p = tid + jj * NTHR;
                int r = p >> 3, jl = p & 7;
                float ii = sGf[r * 33 +      jl];
                float ff = sGf[r * 33 +  8 + jl];
                float gg = sGf[r * 33 + 16 + jl];
                float oo = sGf[r * 33 + 24 + jl];
                float cn = sigmf(ff) * c1s[jj] + sigmf(ii) * tanhf(gg);
                c1s[jj] = cn;
                h1n[r * HID + j0 + jl] = sigmf(oo) * tanhf(cn);
            }
        }
        gbar();

        // ---------- phase B: layer-2 gates + cell ----------
        {
            ll acc[8][4];
            if (slice == 0) {
                #pragma unroll
                for (int i = 0; i < 8; i++)
                    #pragma unroll
                    for (int j = 0; j < 4; j++) {
                        int c = cg * 8 + 2 * j;
                        int base = (c >> 3) * HID + j0 + (c & 7);
                        acc[i][j] = packf2(bih2[base] + bhh2[base],
                                           bih2[base + 1] + bhh2[base + 1]);
                    }
            } else {
                #pragma unroll
                for (int i = 0; i < 8; i++)
                    #pragma unroll
                    for (int j = 0; j < 4; j++) acc[i][j] = packf2(0.f, 0.f);
            }
            gemm_run<true>(acc, h1n, HID, Wih2, HID, 0,
                           j0, 0, slice * 256, 256, sAbuf, sWbuf);
            gemm_run<true>(acc, h2o, HID, Whh2, HID, 0,
                           j0, 0, slice * 256, 256, sAbuf, sWbuf);
            reduce_slices(acc, red);
            __syncthreads();
            if (slice == 0) {
                #pragma unroll
                for (int i = 0; i < 8; i++) {
                    int r = rg + 16 * i;
                    #pragma unroll
                    for (int j = 0; j < 4; j++) {
                        int c = cg * 8 + 2 * j;
                        float2 v = unpackf2(acc[i][j]);
                        sGf[r * 33 + c]     = v.x;
                        sGf[r * 33 + c + 1] = v.y;
                    }
                }
            }
            __syncthreads();
            #pragma unroll
            for (int jj = 0; jj < 4; jj++) {
                int p = tid + jj * NTHR;
                int r = p >> 3, jl = p & 7;
                float ii = sGf[r * 33 +      jl];
                float ff = sGf[r * 33 +  8 + jl];
                float gg = sGf[r * 33 + 16 + jl];
                float oo = sGf[r * 33 + 24 + jl];
                float cn = sigmf(ff) * c2s[jj] + sigmf(ii) * tanhf(gg);
                c2s[jj] = cn;
                h2n[r * HID + j0 + jl] = sigmf(oo) * tanhf(cn);
            }
        }
        gbar();

        // ---------- phase C: logits GEMM + argmax partials (work stealing) ----
        for (;;) {
            __syncthreads();
            if (tid == 0) s_tile = atomicAdd(&g_ctrC[t], 1);
            __syncthreads();
            int tile = s_tile;
            if (tile >= NTILE_C) break;
            int n0 = tile * 32;
            ll acc[8][4];
            if (slice == 0) {
                #pragma unroll
                for (int j = 0; j < 4; j++) {
                    int c = cg * 8 + 2 * j;
                    float b0 = (n0 + c     < VOC) ? bout[n0 + c]     : 0.f;
                    float b1 = (n0 + c + 1 < VOC) ? bout[n0 + c + 1] : 0.f;
                    #pragma unroll
                    for (int i = 0; i < 8; i++) acc[i][j] = packf2(b0, b1);
                }
            } else {
                #pragma unroll
                for (int i = 0; i < 8; i++)
                    #pragma unroll
                    for (int j = 0; j < 4; j++) acc[i][j] = packf2(0.f, 0.f);
            }
            gemm_run<false>(acc, h2n, HID, Wout, HID, 0,
                            n0, VOC - 1, slice * 256, 256, sAbuf, sWbuf);
            reduce_slices(acc, red);
            if (slice == 0) {
                bool full = (n0 + 32 <= VOC);
                #pragma unroll
                for (int i = 0; i < 8; i++) {
                    int r = rg + 16 * i;
                    size_t ob = ((size_t)t * BATCH + r) * VOC + n0 + cg * 8;
                    float2 v0 = unpackf2(acc[i][0]);
                    float2 v1 = unpackf2(acc[i][1]);
                    float2 v2 = unpackf2(acc[i][2]);
                    float2 v3 = unpackf2(acc[i][3]);
                    float vv[8] = {v0.x, v0.y, v1.x, v1.y, v2.x, v2.y, v3.x, v3.y};
                    float bv = -FLT_MAX; int bc = 0x7fffffff;
                    if (full) {
                        __stcs((float4*)(out + ob),     make_float4(vv[0], vv[1], vv[2], vv[3]));
                        __stcs((float4*)(out + ob + 4), make_float4(vv[4], vv[5], vv[6], vv[7]));
                        #pragma unroll
                        for (int q = 0; q < 8; q++)
                            if (vv[q] > bv) { bv = vv[q]; bc = n0 + cg * 8 + q; }
                    } else {
                        #pragma unroll
                        for (int q = 0; q < 8; q++) {
                            int col = n0 + cg * 8 + q;
                            if (col < VOC) {
                                __stcs(out + ((size_t)t * BATCH + r) * VOC + col, vv[q]);
                                if (vv[q] > bv) { bv = vv[q]; bc = col; }
                            }
                        }
                    }
                    #pragma unroll
                    for (int d = 2; d > 0; d >>= 1) {
                        float ov = __shfl_down_sync(0xffffffffu, bv, d, 4);
                        int   oc = __shfl_down_sync(0xffffffffu, bc, d, 4);
                        if (ov > bv || (ov == bv && oc < bc)) { bv = ov; bc = oc; }
                    }
                    if (cg == 0) { g_pmax[r][tile] = bv; g_pidx[r][tile] = bc; }
                }
            }
        }
        gbar();

        // ---------- phase D: final argmax + next-input select ----------
        {
            int b = blk;
            float bv = -FLT_MAX; int bc = 0x7fffffff;
            for (int tile = tid; tile < NTILE_C; tile += NTHR) {
                float v = __ldcg(&g_pmax[b][tile]);
                int   c = __ldcg(&g_pidx[b][tile]);
                if (v > bv || (v == bv && c < bc)) { bv = v; bc = c; }
            }
            s_rv[tid] = bv; s_ri[tid] = bc;
            __syncthreads();
            for (int s = NTHR / 2; s > 0; s >>= 1) {
                if (tid < s) {
                    float v = s_rv[tid + s]; int c = s_ri[tid + s];
                    if (v > s_rv[tid] || (v == s_rv[tid] && c < s_ri[tid])) {
                        s_rv[tid] = v; s_ri[tid] = c;
                    }
                }
                __syncthreads();
            }
            if (tid == 0) {
                int m = tfmask[t * BATCH + b];
                int tok; float sc;
                if (m == 1) { tok = s_ri[0]; sc = 1.0f; }
                else        { tok = expanded[b * SEQT + t + 1]; sc = dropm[tok]; }
                s_tok = tok; s_sc = sc;
            }
            __syncthreads();
            int tok = s_tok; float sc = s_sc;
            for (int e = tid; e < EMB; e += NTHR)
                g_x[b * EMB + e] = sc * embW[(size_t)tok * EMB + e];
        }
        gbar();
    }
}

extern "C" void kernel_launch(void* const* d_in, const int* in_sizes, int n_in,
                              void* d_out, int out_size) {
    (void)in_sizes; (void)n_in; (void)out_size;
    lstm_kernel<<<NBLK, NTHR>>>(
        (const float*)d_in[0],  (const int*)d_in[1],  (const int*)d_in[2],
        (const float*)d_in[3],  (const float*)d_in[4], (const float*)d_in[5],
        (const float*)d_in[6],  (const float*)d_in[7], (const float*)d_in[8],
        (const float*)d_in[9],  (const float*)d_in[10], (const float*)d_in[11],
        (const float*)d_in[12], (const float*)d_in[13], (const float*)d_in[14],
        (float*)d_out);
}